// round 13
// baseline (speedup 1.0000x reference)
#include <cuda_runtime.h>
#include <cuda_bf16.h>
#include <stdint.h>
#include <math.h>

// ---------------------------------------------------------------------------
// MySelfAttention_V2 (B=4, N=4096, D=768) — mma.sync bf16 hi/lo split (3-pass)
// R13: barrier-free GEMM. Each warp stages its own operand slice via cp.async
//      into a private 12KB/stage smem region (2 stages); main loop is
//      wait_group -> syncwarp -> ldsm -> 96-MMA burst -> prefetch. No
//      __syncthreads in the mainloop. 1 CTA x 256 thr, 192KB smem.
//      Launch graph (2 streams, per-batch chains) identical to R12.
// ---------------------------------------------------------------------------

#define B_   4
#define N_   4096
#define D_   768
#define QKVC 2304
#define SCALE_F 0.03608439182435161f

typedef __nv_bfloat16 bf16;

// ---------------- scratch (static device globals: allocation-guard-safe) ----
__device__ float g_s    [(size_t)B_ * N_ * N_];
__device__ bf16  g_xh   [(size_t)B_ * N_ * D_],  g_xl  [(size_t)B_ * N_ * D_];
__device__ bf16  g_wrh  [(size_t)D_ * QKVC],     g_wrl [(size_t)D_ * QKVC];
__device__ bf16  g_mth  [(size_t)D_ * D_],       g_mtl [(size_t)D_ * D_];
__device__ bf16  g_wvh  [(size_t)D_ * D_],       g_wvl [(size_t)D_ * D_];
__device__ bf16  g_vh   [(size_t)B_ * N_ * D_],  g_vl  [(size_t)B_ * N_ * D_];
__device__ bf16  g_yh   [(size_t)B_ * N_ * D_],  g_yl  [(size_t)B_ * N_ * D_];
__device__ bf16  g_sh   [(size_t)B_ * N_ * N_],  g_sl  [(size_t)B_ * N_ * N_];
__device__ bf16  g_vth  [(size_t)B_ * D_ * N_],  g_vtl [(size_t)B_ * D_ * N_];
__device__ bf16  g_ch   [(size_t)B_ * N_ * D_],  g_cl  [(size_t)B_ * N_ * D_];
__device__ bf16  g_woh  [(size_t)D_ * D_],       g_wol [(size_t)D_ * D_];
__device__ float g_wv   [D_];
__device__ float g_cvec [(size_t)B_ * N_];

// ---------------- PTX helpers ----------------------------------------------
static __device__ __forceinline__ uint32_t smem_u32(const void* p) {
    uint32_t a;
    asm("{ .reg .u64 t; cvta.to.shared.u64 t, %1; cvt.u32.u64 %0, t; }"
        : "=r"(a) : "l"(p));
    return a;
}
static __device__ __forceinline__ void cp_async16(uint32_t saddr, const void* g) {
    asm volatile("cp.async.cg.shared.global [%0], [%1], 16;"
                 :: "r"(saddr), "l"(g) : "memory");
}
static __device__ __forceinline__ void cp_commit() {
    asm volatile("cp.async.commit_group;" ::: "memory");
}
template <int N>
static __device__ __forceinline__ void cp_wait() {
    asm volatile("cp.async.wait_group %0;" :: "n"(N) : "memory");
}
static __device__ __forceinline__ void ldsm_x4(uint32_t* r, uint32_t addr) {
    asm volatile("ldmatrix.sync.aligned.m8n8.x4.shared.b16 {%0,%1,%2,%3}, [%4];"
                 : "=r"(r[0]), "=r"(r[1]), "=r"(r[2]), "=r"(r[3]) : "r"(addr));
}
static __device__ __forceinline__ void mma16816(float* c, const uint32_t* a,
                                                const uint32_t* b) {
    asm volatile(
        "mma.sync.aligned.m16n8k16.row.col.f32.bf16.bf16.f32 "
        "{%0,%1,%2,%3}, {%4,%5,%6,%7}, {%8,%9}, {%0,%1,%2,%3};"
        : "+f"(c[0]), "+f"(c[1]), "+f"(c[2]), "+f"(c[3])
        : "r"(a[0]), "r"(a[1]), "r"(a[2]), "r"(a[3]), "r"(b[0]), "r"(b[1]));
}
static __device__ __forceinline__ void split1(float v, bf16& h, bf16& l) {
    h = __float2bfloat16_rn(v);
    l = __float2bfloat16_rn(v - __bfloat162float(h));
}
static __device__ __forceinline__ uint32_t pack2(bf16 a, bf16 b) {
    return (uint32_t)__bfloat16_as_ushort(a) |
           ((uint32_t)__bfloat16_as_ushort(b) << 16);
}
static __device__ __forceinline__ uint32_t swz(uint32_t row, uint32_t chunk) {
    return row * 64u + (((chunk ^ (row >> 1)) & 3u) << 4);
}

// ---------------------------------------------------------------------------
// Barrier-free GEMM: C[m,n] = alpha * sum_k A[m,k]*B[n,k] (+bias[n])
// CTA tile 128x128, BK=32, 256 thr (2x4 warps, warp tile 64x32).
// Per-warp private staging: A-slice(64 rows) hi/lo 8KB + B-slice(32 rows)
// hi/lo 4KB = 12KB/stage, 2 stages, 8 warps -> 192KB smem, 1 CTA/SM.
// ---------------------------------------------------------------------------
#define WSTAGE 12288                       // bytes per warp per stage
#define WREGION (2 * WSTAGE)               // per-warp region (2 stages)
static const int SMEM_DYN = 8 * WREGION;   // 196608

template <bool HAS_BIAS, bool WRITE_F32, bool WRITE_SPLIT>
__global__ __launch_bounds__(256, 1)
void mma_gemm(const bf16* __restrict__ Ah, const bf16* __restrict__ Al,
              const bf16* __restrict__ Bh, const bf16* __restrict__ Bl,
              const float* __restrict__ bias, float* __restrict__ C,
              bf16* __restrict__ Oh, bf16* __restrict__ Ol,
              int K, int lda, int ldb, int ldc,
              long long sA, long long sB, long long sC, long long sBias,
              float alpha)
{
    extern __shared__ char smem[];
    const uint32_t sb = smem_u32(smem);

    Ah += blockIdx.z * sA;  Al += blockIdx.z * sA;
    Bh += blockIdx.z * sB;  Bl += blockIdx.z * sB;
    if (HAS_BIAS) bias += blockIdx.z * sBias;
    const long long cz = blockIdx.z * sC;
    const int m0 = blockIdx.y * 128, n0 = blockIdx.x * 128;
    const int tid  = threadIdx.x;
    const int wid  = tid >> 5, lane = tid & 31;
    const int wm   = wid >> 2, wn = wid & 3;       // 2 x 4 warps

    const uint32_t wb = sb + (uint32_t)wid * WREGION;

    // per-warp staged load of its own A(64 rows) + B(32 rows) hi/lo slices
#define LOAD_STAGE(stg, k0)                                                     \
    do {                                                                        \
        const uint32_t sbase = wb + (uint32_t)(stg) * WSTAGE;                   \
        _Pragma("unroll")                                                       \
        for (int i = 0; i < 8; i++) {                                           \
            const int idx = i * 32 + lane;                                      \
            const int row = idx >> 2, c = idx & 3;                              \
            const long long g = (long long)(m0 + wm * 64 + row) * lda           \
                                + (k0) + c * 8;                                 \
            const uint32_t d = sbase + swz((uint32_t)row, (uint32_t)c);         \
            cp_async16(d,         Ah + g);                                      \
            cp_async16(d + 4096u, Al + g);                                      \
        }                                                                       \
        _Pragma("unroll")                                                       \
        for (int i = 0; i < 4; i++) {                                           \
            const int idx = i * 32 + lane;                                      \
            const int row = idx >> 2, c = idx & 3;                              \
            const long long g = (long long)(n0 + wn * 32 + row) * ldb           \
                                + (k0) + c * 8;                                 \
            const uint32_t d = sbase + 8192u + swz((uint32_t)row, (uint32_t)c); \
            cp_async16(d,         Bh + g);                                      \
            cp_async16(d + 2048u, Bl + g);                                      \
        }                                                                       \
    } while (0)

    const uint32_t a_row_l = (uint32_t)(lane & 15);
    const uint32_t a_chk_l = (uint32_t)(lane >> 4);
    const uint32_t b_row_l = (uint32_t)((lane & 7) + ((lane >> 4) << 3));
    const uint32_t b_chk_l = (uint32_t)((lane >> 3) & 1);

    float acc[4][4][4];
#pragma unroll
    for (int mt = 0; mt < 4; mt++)
#pragma unroll
        for (int nt = 0; nt < 4; nt++)
#pragma unroll
            for (int r = 0; r < 4; r++) acc[mt][nt][r] = 0.0f;

    const int nch = K / 32;
    LOAD_STAGE(0, 0);
    cp_commit();
    LOAD_STAGE(1, 32);
    cp_commit();

    for (int ch = 0; ch < nch; ch++) {
        cp_wait<1>();            // this warp's group `ch` resident
        __syncwarp();            // cross-lane visibility for ldmatrix

        const uint32_t base = wb + (uint32_t)(ch & 1) * WSTAGE;

        uint32_t af[2][2][4][4];     // [kk][plane][mt][reg]
        uint32_t bf_[2][2][2][4];    // [kk][plane][pair][reg]
#pragma unroll
        for (int kk = 0; kk < 2; kk++) {
            const uint32_t a_chk = (uint32_t)(kk * 2) + a_chk_l;
            const uint32_t b_chk = (uint32_t)(kk * 2) + b_chk_l;
#pragma unroll
            for (int mt = 0; mt < 4; mt++) {
                const uint32_t ro = swz((uint32_t)(mt * 16) + a_row_l, a_chk);
                ldsm_x4(af[kk][0][mt], base + ro);
                ldsm_x4(af[kk][1][mt], base + 4096u + ro);
            }
#pragma unroll
            for (int p = 0; p < 2; p++) {
                const uint32_t ro = swz((uint32_t)(p * 16) + b_row_l, b_chk);
                ldsm_x4(bf_[kk][0][p], base + 8192u + ro);
                ldsm_x4(bf_[kk][1][p], base + 10240u + ro);
            }
        }

        // 96 MMAs: per kk, passes (Ah,Bh), (Ah,Bl), (Al,Bh) — same order
        // as prior rounds => bit-identical accumulation
#pragma unroll
        for (int kk = 0; kk < 2; kk++)
#pragma unroll
            for (int ps = 0; ps < 3; ps++) {
                const int ah = (ps == 2), bh = (ps == 1);
#pragma unroll
                for (int mt = 0; mt < 4; mt++)
#pragma unroll
                    for (int nt = 0; nt < 4; nt++)
                        mma16816(acc[mt][nt], af[kk][ah][mt],
                                 &bf_[kk][bh][nt >> 1][(nt & 1) * 2]);
            }

        // prefetch chunk ch+2 into the stage just consumed (MMA issue has
        // drained the ldsm scoreboard, so smem reads are complete)
        if (ch + 2 < nch) LOAD_STAGE(ch & 1, (long long)(ch + 2) * 32);
        cp_commit();
    }

    // ---- epilogue (no barrier needed: acc in registers) ----
    const int tq = lane >> 2, tr = lane & 3;
#pragma unroll
    for (int nt = 0; nt < 4; nt++) {
        const int n = n0 + wn * 32 + nt * 8 + tr * 2;
        float b0 = 0.f, b1 = 0.f;
        if (HAS_BIAS) { b0 = bias[n]; b1 = bias[n + 1]; }
#pragma unroll
        for (int mt = 0; mt < 4; mt++) {
            const int m = m0 + wm * 64 + mt * 16 + tq;
            float2 o0, o1;
            o0.x = fmaf(alpha, acc[mt][nt][0], b0);
            o0.y = fmaf(alpha, acc[mt][nt][1], b1);
            o1.x = fmaf(alpha, acc[mt][nt][2], b0);
            o1.y = fmaf(alpha, acc[mt][nt][3], b1);
            const long long r0 = cz + (long long)m * ldc + n;
            const long long r1 = cz + (long long)(m + 8) * ldc + n;
            if (WRITE_F32) {
                *(float2*)(C + r0) = o0;
                *(float2*)(C + r1) = o1;
            }
            if (WRITE_SPLIT) {
                bf16 h0, l0, h1, l1;
                split1(o0.x, h0, l0); split1(o0.y, h1, l1);
                *(uint32_t*)(Oh + r0) = pack2(h0, h1);
                *(uint32_t*)(Ol + r0) = pack2(l0, l1);
                split1(o1.x, h0, l0); split1(o1.y, h1, l1);
                *(uint32_t*)(Oh + r1) = pack2(h0, h1);
                *(uint32_t*)(Ol + r1) = pack2(l0, l1);
            }
        }
    }
#undef LOAD_STAGE
}

// ---------------------------------------------------------------------------
__global__ __launch_bounds__(256)
void split_kernel(const float* __restrict__ in, bf16* __restrict__ oh,
                  bf16* __restrict__ ol)
{
    const size_t i = ((size_t)blockIdx.x * 256 + threadIdx.x) * 4;
    const float4 v = *(const float4*)(in + i);
    bf16 h0, h1, h2, h3, l0, l1, l2, l3;
    split1(v.x, h0, l0); split1(v.y, h1, l1);
    split1(v.z, h2, l2); split1(v.w, h3, l3);
    *(uint2*)(oh + i) = make_uint2(pack2(h0, h1), pack2(h2, h3));
    *(uint2*)(ol + i) = make_uint2(pack2(l0, l1), pack2(l2, l3));
}

// ---------------------------------------------------------------------------
__global__ __launch_bounds__(256)
void transpose_split(const float* __restrict__ in, int ldin, long long sIn,
                     bf16* __restrict__ oh, bf16* __restrict__ ol,
                     int R, long long sOut)
{
    __shared__ float t[32][33];
    in += blockIdx.z * sIn;
    oh += blockIdx.z * sOut;
    ol += blockIdx.z * sOut;
    const int c0 = blockIdx.x * 32, r0 = blockIdx.y * 32;
    const int x = threadIdx.x, y = threadIdx.y;
#pragma unroll
    for (int j = 0; j < 32; j += 8)
        t[y + j][x] = in[(long long)(r0 + y + j) * ldin + c0 + x];
    __syncthreads();
#pragma unroll
    for (int j = 0; j < 32; j += 8) {
        const float v = t[x][y + j];
        bf16 h, l;
        split1(v, h, l);
        oh[(long long)(c0 + y + j) * R + r0 + x] = h;
        ol[(long long)(c0 + y + j) * R + r0 + x] = l;
    }
}

// ---------------------------------------------------------------------------
__global__ __launch_bounds__(256)
void transpose_bf16_2(const bf16* __restrict__ inh, const bf16* __restrict__ inl,
                      int ldin, long long sIn,
                      bf16* __restrict__ oh, bf16* __restrict__ ol,
                      int R, long long sOut)
{
    __shared__ bf16 th[32][33];
    __shared__ bf16 tl[32][33];
    inh += blockIdx.z * sIn;
    inl += blockIdx.z * sIn;
    oh  += blockIdx.z * sOut;
    ol  += blockIdx.z * sOut;
    const int c0 = blockIdx.x * 32, r0 = blockIdx.y * 32;
    const int x = threadIdx.x, y = threadIdx.y;
#pragma unroll
    for (int j = 0; j < 32; j += 8) {
        th[y + j][x] = inh[(long long)(r0 + y + j) * ldin + c0 + x];
        tl[y + j][x] = inl[(long long)(r0 + y + j) * ldin + c0 + x];
    }
    __syncthreads();
#pragma unroll
    for (int j = 0; j < 32; j += 8) {
        oh[(long long)(c0 + y + j) * R + r0 + x] = th[x][y + j];
        ol[(long long)(c0 + y + j) * R + r0 + x] = tl[x][y + j];
    }
}

// ---------------------------------------------------------------------------
__global__ __launch_bounds__(256)
void wvec_kernel(const float* __restrict__ w_qkv, const float* __restrict__ bq,
                 float* __restrict__ wv)
{
    __shared__ float red[8];
    const int d = blockIdx.x;
    const float* rowp = w_qkv + (size_t)d * QKVC + D_;
    float s = 0.0f;
    for (int a = threadIdx.x; a < D_; a += 256) s += rowp[a] * bq[a];
#pragma unroll
    for (int o = 16; o > 0; o >>= 1) s += __shfl_xor_sync(0xffffffffu, s, o);
    if (!(threadIdx.x & 31)) red[threadIdx.x >> 5] = s;
    __syncthreads();
    if (threadIdx.x == 0) {
        float t = 0.0f;
#pragma unroll
        for (int i = 0; i < 8; i++) t += red[i];
        wv[d] = t;
    }
}

// ---------------------------------------------------------------------------
__global__ __launch_bounds__(256)
void cvec_kernel(const float* __restrict__ x, const float* __restrict__ wv,
                 float* __restrict__ c)
{
    const int row = blockIdx.x * 8 + (threadIdx.x >> 5);
    const int lane = threadIdx.x & 31;
    const float* xr = x + (size_t)row * D_;
    float s = 0.0f;
    for (int d = lane; d < D_; d += 32) s += xr[d] * wv[d];
#pragma unroll
    for (int o = 16; o > 0; o >>= 1) s += __shfl_xor_sync(0xffffffffu, s, o);
    if (lane == 0) c[row] = s * SCALE_F;
}

// ---------------------------------------------------------------------------
__global__ __launch_bounds__(256)
void softmax_split_kernel(const float* __restrict__ S, bf16* __restrict__ Sh,
                          bf16* __restrict__ Sl)
{
    const size_t ro = (size_t)blockIdx.x * N_;
    const float* p = S + ro;
    const int tid = threadIdx.x;
    const int w = tid >> 5, l = tid & 31;

    float4 v[4];
#pragma unroll
    for (int i = 0; i < 4; i++)
        v[i] = *(const float4*)(p + (size_t)(tid + i * 256) * 4);

    float m = v[0].x;
#pragma unroll
    for (int i = 0; i < 4; i++) {
        m = fmaxf(m, v[i].x); m = fmaxf(m, v[i].y);
        m = fmaxf(m, v[i].z); m = fmaxf(m, v[i].w);
    }
#pragma unroll
    for (int o = 16; o > 0; o >>= 1)
        m = fmaxf(m, __shfl_xor_sync(0xffffffffu, m, o));

    __shared__ float red[8];
    if (l == 0) red[w] = m;
    __syncthreads();
    float bm = red[0];
#pragma unroll
    for (int i = 1; i < 8; i++) bm = fmaxf(bm, red[i]);
    __syncthreads();

    float s = 0.0f;
#pragma unroll
    for (int i = 0; i < 4; i++) {
        v[i].x = expf(v[i].x - bm); s += v[i].x;
        v[i].y = expf(v[i].y - bm); s += v[i].y;
        v[i].z = expf(v[i].z - bm); s += v[i].z;
        v[i].w = expf(v[i].w - bm); s += v[i].w;
    }
#pragma unroll
    for (int o = 16; o > 0; o >>= 1)
        s += __shfl_xor_sync(0xffffffffu, s, o);
    if (l == 0) red[w] = s;
    __syncthreads();
    float tot = red[0];
#pragma unroll
    for (int i = 1; i < 8; i++) tot += red[i];
    const float inv = 1.0f / tot;

#pragma unroll
    for (int i = 0; i < 4; i++) {
        const size_t o = ro + (size_t)(tid + i * 256) * 4;
        bf16 h0, h1, h2, h3, l0, l1, l2, l3;
        split1(v[i].x * inv, h0, l0);
        split1(v[i].y * inv, h1, l1);
        split1(v[i].z * inv, h2, l2);
        split1(v[i].w * inv, h3, l3);
        *(uint2*)(Sh + o) = make_uint2(pack2(h0, h1), pack2(h2, h3));
        *(uint2*)(Sl + o) = make_uint2(pack2(l0, l1), pack2(l2, l3));
    }
}

// ---------------------------------------------------------------------------
extern "C" void kernel_launch(void* const* d_in, const int* in_sizes, int n_in,
                              void* d_out, int out_size)
{
    const float* x     = (const float*)d_in[0];
    const float* w_qkv = (const float*)d_in[1];
    const float* b_qkv = (const float*)d_in[2];
    const float* w_out = (const float*)d_in[3];
    const float* b_out = (const float*)d_in[4];
    float* out = (float*)d_out;

    float *S, *wv, *cvec;
    bf16 *xh, *xl, *wrh, *wrl, *mth, *mtl, *wvh, *wvl, *vh, *vl, *yh, *yl;
    bf16 *sh, *sl, *vth, *vtl, *ch, *cl, *woh, *wol;
    cudaGetSymbolAddress((void**)&S,    g_s);
    cudaGetSymbolAddress((void**)&wv,   g_wv);
    cudaGetSymbolAddress((void**)&cvec, g_cvec);
    cudaGetSymbolAddress((void**)&xh,   g_xh);  cudaGetSymbolAddress((void**)&xl,  g_xl);
    cudaGetSymbolAddress((void**)&wrh,  g_wrh); cudaGetSymbolAddress((void**)&wrl, g_wrl);
    cudaGetSymbolAddress((void**)&mth,  g_mth); cudaGetSymbolAddress((void**)&mtl, g_mtl);
    cudaGetSymbolAddress((void**)&wvh,  g_wvh); cudaGetSymbolAddress((void**)&wvl, g_wvl);
    cudaGetSymbolAddress((void**)&vh,   g_vh);  cudaGetSymbolAddress((void**)&vl,  g_vl);
    cudaGetSymbolAddress((void**)&yh,   g_yh);  cudaGetSymbolAddress((void**)&yl,  g_yl);
    cudaGetSymbolAddress((void**)&sh,   g_sh);  cudaGetSymbolAddress((void**)&sl,  g_sl);
    cudaGetSymbolAddress((void**)&vth,  g_vth); cudaGetSymbolAddress((void**)&vtl, g_vtl);
    cudaGetSymbolAddress((void**)&ch,   g_ch);  cudaGetSymbolAddress((void**)&cl,  g_cl);
    cudaGetSymbolAddress((void**)&woh,  g_woh); cudaGetSymbolAddress((void**)&wol, g_wol);

    cudaFuncSetAttribute(mma_gemm<true, false, true>,
        cudaFuncAttributeMaxDynamicSharedMemorySize, SMEM_DYN);
    cudaFuncSetAttribute(mma_gemm<false, false, true>,
        cudaFuncAttributeMaxDynamicSharedMemorySize, SMEM_DYN);
    cudaFuncSetAttribute(mma_gemm<true, true, false>,
        cudaFuncAttributeMaxDynamicSharedMemorySize, SMEM_DYN);

    // ONE side stream (known-guard-legal footprint) + events
    static cudaStream_t sv = nullptr;
    static cudaEvent_t eRoot = nullptr, eX = nullptr, eMain = nullptr,
                       eV = nullptr, eSv = nullptr;
    if (!sv) {
        cudaStreamCreateWithFlags(&sv, cudaStreamNonBlocking);
        cudaEventCreateWithFlags(&eRoot, cudaEventDisableTiming);
        cudaEventCreateWithFlags(&eX,    cudaEventDisableTiming);
        cudaEventCreateWithFlags(&eMain, cudaEventDisableTiming);
        cudaEventCreateWithFlags(&eV,    cudaEventDisableTiming);
        cudaEventCreateWithFlags(&eSv,   cudaEventDisableTiming);
    }

    const dim3 blk(256);
    const dim3 tblk(32, 8);
    const long long ND = (long long)N_ * D_;
    const long long NN = (long long)N_ * N_;
    const long long DN = (long long)D_ * N_;

    // ---- fork sv ----
    cudaEventRecord(eRoot, 0);
    cudaStreamWaitEvent(sv, eRoot, 0);

    // sv: weight transposes (inputs only)
    transpose_split<<<dim3(D_ / 32, D_ / 32, 1), tblk, 0, sv>>>(
        w_qkv + 2 * D_, QKVC, 0, wvh, wvl, D_, 0);                // Wv^T
    transpose_split<<<dim3(D_ / 32, D_ / 32, 1), tblk, 0, sv>>>(
        w_out, D_, 0, woh, wol, D_, 0);                           // Wo^T

    // main: x split, weight row split, bias vectors, Mt
    split_kernel<<<(B_ * N_ * D_) / 1024, blk>>>(x, xh, xl);
    cudaEventRecord(eX, 0);
    split_kernel<<<(D_ * QKVC) / 1024, blk>>>(w_qkv, wrh, wrl);
    wvec_kernel<<<D_, blk>>>(w_qkv, b_qkv, wv);
    cvec_kernel<<<(B_ * N_) / 8, blk>>>(x, wv, cvec);
    mma_gemm<false, false, true><<<dim3(D_ / 128, D_ / 128, 1), blk, SMEM_DYN>>>(
        wrh + D_, wrl + D_, wrh, wrl, nullptr, nullptr, mth, mtl,
        D_, QKVC, QKVC, D_, 0, 0, 0, 0, 1.0f);
    cudaEventRecord(eMain, 0);   // covers xh/xl, cvec, Mt

    // sv: V GEMM + V^T (needs xh/xl)
    cudaStreamWaitEvent(sv, eX, 0);
    mma_gemm<true, false, true><<<dim3(D_ / 128, (B_ * N_) / 128, 1), blk, SMEM_DYN, sv>>>(
        xh, xl, wvh, wvl, b_qkv + 2 * D_, nullptr, vh, vl,
        D_, D_, D_, D_, 0, 0, 0, 0, 1.0f);
    transpose_bf16_2<<<dim3(D_ / 32, N_ / 32, B_), tblk, 0, sv>>>(
        vh, vl, D_, ND, vth, vtl, N_, DN);
    cudaEventRecord(eV, sv);

    // ---- per-batch chains: batches 0,2 on stream 0; batches 1,3 on sv ----
    cudaStreamWaitEvent(0,  eV,    0);
    cudaStreamWaitEvent(sv, eMain, 0);

    for (int b = 0; b < B_; b++) {
        cudaStream_t cs = (b & 1) ? sv : (cudaStream_t)0;
        const long long oND = (long long)b * ND;
        const long long oNN = (long long)b * NN;
        const long long oDN = (long long)b * DN;

        // y_b = x_b @ Mt^T
        mma_gemm<false, false, true><<<dim3(D_ / 128, N_ / 128, 1), blk, SMEM_DYN, cs>>>(
            xh + oND, xl + oND, mth, mtl, nullptr, nullptr, yh + oND, yl + oND,
            D_, D_, D_, D_, 0, 0, 0, 0, 1.0f);

        // S_b = scale*(y_b x_b^T) + cvec_b
        mma_gemm<true, true, false><<<dim3(N_ / 128, N_ / 128, 1), blk, SMEM_DYN, cs>>>(
            yh + oND, yl + oND, xh + oND, xl + oND, cvec + (long long)b * N_,
            S + oNN, nullptr, nullptr,
            D_, D_, D_, N_, 0, 0, 0, 0, SCALE_F);

        // softmax_b + split
        softmax_split_kernel<<<N_, blk, 0, cs>>>(S + oNN, sh + oNN, sl + oNN);

        // PV_b
        mma_gemm<false, false, true><<<dim3(D_ / 128, N_ / 128, 1), blk, SMEM_DYN, cs>>>(
            sh + oNN, sl + oNN, vth + oDN, vtl + oDN, nullptr, nullptr,
            ch + oND, cl + oND, N_, N_, N_, D_, 0, 0, 0, 0, 1.0f);

        // out_b = ctx_b @ Wo + bo
        mma_gemm<true, true, false><<<dim3(D_ / 128, N_ / 128, 1), blk, SMEM_DYN, cs>>>(
            ch + oND, cl + oND, woh, wol, b_out, out + oND, nullptr, nullptr,
            D_, D_, D_, D_, 0, 0, 0, 0, 1.0f);
    }

    // ---- join sv back to the capture stream ----
    cudaEventRecord(eSv, sv);
    cudaStreamWaitEvent(0, eSv, 0);
}

// round 15
// speedup vs baseline: 1.0264x; 1.0264x over previous
#include <cuda_runtime.h>
#include <cuda_bf16.h>
#include <stdint.h>
#include <math.h>

// ---------------------------------------------------------------------------
// MySelfAttention_V2 (B=4, N=4096, D=768) — mma.sync bf16 hi/lo split (3-pass)
// R14: revert to the R12 GEMM core (confirmed local optimum: 128x128/BK32,
//      3-stage cp.async, 2 CTA/SM). Graph fix: V projection merged into the
//      per-batch y GEMM via a combined B operand bc=[Mt ; Wv^T] and
//      concatenated bias [0, b_v] — removes the eV join that stalled
//      stream-0 chains behind the whole V path. Numerics identical.
// ---------------------------------------------------------------------------

#define B_   4
#define N_   4096
#define D_   768
#define QKVC 2304
#define NCAT 1536                       // cols of combined y|V output
#define SCALE_F 0.03608439182435161f

typedef __nv_bfloat16 bf16;

// ---------------- scratch (static device globals: allocation-guard-safe) ----
__device__ float g_s    [(size_t)B_ * N_ * N_];
__device__ bf16  g_xh   [(size_t)B_ * N_ * D_],   g_xl  [(size_t)B_ * N_ * D_];
__device__ bf16  g_wrh  [(size_t)D_ * QKVC],      g_wrl [(size_t)D_ * QKVC];
__device__ bf16  g_bch  [(size_t)NCAT * D_],      g_bcl [(size_t)NCAT * D_];
__device__ bf16  g_yvh  [(size_t)B_ * N_ * NCAT], g_yvl [(size_t)B_ * N_ * NCAT];
__device__ bf16  g_sh   [(size_t)B_ * N_ * N_],   g_sl  [(size_t)B_ * N_ * N_];
__device__ bf16  g_vth  [(size_t)B_ * D_ * N_],   g_vtl [(size_t)B_ * D_ * N_];
__device__ bf16  g_ch   [(size_t)B_ * N_ * D_],   g_cl  [(size_t)B_ * N_ * D_];
__device__ bf16  g_woh  [(size_t)D_ * D_],        g_wol [(size_t)D_ * D_];
__device__ float g_wv   [D_];
__device__ float g_cvec [(size_t)B_ * N_];
__device__ float g_bcat [NCAT];

// ---------------- PTX helpers ----------------------------------------------
static __device__ __forceinline__ uint32_t smem_u32(const void* p) {
    uint32_t a;
    asm("{ .reg .u64 t; cvta.to.shared.u64 t, %1; cvt.u32.u64 %0, t; }"
        : "=r"(a) : "l"(p));
    return a;
}
static __device__ __forceinline__ void cp_async16(uint32_t saddr, const void* g) {
    asm volatile("cp.async.cg.shared.global [%0], [%1], 16;"
                 :: "r"(saddr), "l"(g) : "memory");
}
static __device__ __forceinline__ void cp_commit() {
    asm volatile("cp.async.commit_group;" ::: "memory");
}
template <int N>
static __device__ __forceinline__ void cp_wait() {
    asm volatile("cp.async.wait_group %0;" :: "n"(N) : "memory");
}
static __device__ __forceinline__ void ldsm_x4(uint32_t* r, uint32_t addr) {
    asm volatile("ldmatrix.sync.aligned.m8n8.x4.shared.b16 {%0,%1,%2,%3}, [%4];"
                 : "=r"(r[0]), "=r"(r[1]), "=r"(r[2]), "=r"(r[3]) : "r"(addr));
}
static __device__ __forceinline__ void mma16816(float* c, const uint32_t* a,
                                                const uint32_t* b) {
    asm volatile(
        "mma.sync.aligned.m16n8k16.row.col.f32.bf16.bf16.f32 "
        "{%0,%1,%2,%3}, {%4,%5,%6,%7}, {%8,%9}, {%0,%1,%2,%3};"
        : "+f"(c[0]), "+f"(c[1]), "+f"(c[2]), "+f"(c[3])
        : "r"(a[0]), "r"(a[1]), "r"(a[2]), "r"(a[3]), "r"(b[0]), "r"(b[1]));
}
static __device__ __forceinline__ void split1(float v, bf16& h, bf16& l) {
    h = __float2bfloat16_rn(v);
    l = __float2bfloat16_rn(v - __bfloat162float(h));
}
static __device__ __forceinline__ uint32_t pack2(bf16 a, bf16 b) {
    return (uint32_t)__bfloat16_as_ushort(a) |
           ((uint32_t)__bfloat16_as_ushort(b) << 16);
}
static __device__ __forceinline__ uint32_t swz(uint32_t row, uint32_t chunk) {
    return row * 64u + (((chunk ^ (row >> 1)) & 3u) << 4);
}

// ---------------------------------------------------------------------------
// GEMM (R12 core): C[m,n] = alpha * sum_k A[m,k]*B[n,k] (+bias[n])
// ---------------------------------------------------------------------------
#define TILE_B 8192                       // 128 rows * 64 B
#define STAGE_B (4 * TILE_B)              // Ah,Al,Bh,Bl
static const int SMEM_DYN = 3 * STAGE_B;  // 98304

template <bool HAS_BIAS, bool WRITE_F32, bool WRITE_SPLIT>
__global__ __launch_bounds__(256, 2)
void mma_gemm(const bf16* __restrict__ Ah, const bf16* __restrict__ Al,
              const bf16* __restrict__ Bh, const bf16* __restrict__ Bl,
              const float* __restrict__ bias, float* __restrict__ C,
              bf16* __restrict__ Oh, bf16* __restrict__ Ol,
              int K, int lda, int ldb, int ldc,
              long long sA, long long sB, long long sC, long long sBias,
              float alpha)
{
    extern __shared__ char smem[];
    const uint32_t sb = smem_u32(smem);

    Ah += blockIdx.z * sA;  Al += blockIdx.z * sA;
    Bh += blockIdx.z * sB;  Bl += blockIdx.z * sB;
    if (HAS_BIAS) bias += blockIdx.z * sBias;
    const long long cz = blockIdx.z * sC;
    const int m0 = blockIdx.y * 128, n0 = blockIdx.x * 128;
    const int tid  = threadIdx.x;
    const int wid  = tid >> 5, lane = tid & 31;
    const int wm   = wid >> 2, wn = wid & 3;   // 2 x 4 warps

    const int cr0 = tid >> 2, cc = tid & 3;
    const uint32_t so0 = swz((uint32_t)cr0, (uint32_t)cc);
    const uint32_t so1 = swz((uint32_t)(cr0 + 64), (uint32_t)cc);

#define LOAD_STAGE(st, k0)                                                      \
    do {                                                                        \
        const uint32_t s0 = sb + (uint32_t)(st) * STAGE_B;                      \
        const long long kof = (long long)(k0) + cc * 8;                         \
        cp_async16(s0 + 0*TILE_B + so0, Ah + (long long)(m0+cr0)    *lda + kof);\
        cp_async16(s0 + 0*TILE_B + so1, Ah + (long long)(m0+cr0+64) *lda + kof);\
        cp_async16(s0 + 1*TILE_B + so0, Al + (long long)(m0+cr0)    *lda + kof);\
        cp_async16(s0 + 1*TILE_B + so1, Al + (long long)(m0+cr0+64) *lda + kof);\
        cp_async16(s0 + 2*TILE_B + so0, Bh + (long long)(n0+cr0)    *ldb + kof);\
        cp_async16(s0 + 2*TILE_B + so1, Bh + (long long)(n0+cr0+64) *ldb + kof);\
        cp_async16(s0 + 3*TILE_B + so0, Bl + (long long)(n0+cr0)    *ldb + kof);\
        cp_async16(s0 + 3*TILE_B + so1, Bl + (long long)(n0+cr0+64) *ldb + kof);\
    } while (0)

    const uint32_t a_row_l = (uint32_t)(lane & 15);
    const uint32_t a_chk_l = (uint32_t)(lane >> 4);
    const uint32_t b_row_l = (uint32_t)((lane & 7) + ((lane >> 4) << 3));
    const uint32_t b_chk_l = (uint32_t)((lane >> 3) & 1);

    float acc[4][4][4];
#pragma unroll
    for (int mt = 0; mt < 4; mt++)
#pragma unroll
        for (int nt = 0; nt < 4; nt++)
#pragma unroll
            for (int r = 0; r < 4; r++) acc[mt][nt][r] = 0.0f;

    const int nch = K / 32;
    LOAD_STAGE(0, 0);
    cp_commit();
    if (nch > 1) LOAD_STAGE(1, 32);
    cp_commit();

    int st = 0, ls = 2;
    for (int ch = 0; ch < nch; ch++) {
        cp_wait<1>();
        __syncthreads();
        if (ch + 2 < nch) LOAD_STAGE(ls, (long long)(ch + 2) * 32);
        cp_commit();

        const uint32_t base = sb + (uint32_t)st * STAGE_B;
#pragma unroll
        for (int kk = 0; kk < 2; kk++) {
            uint32_t af[2][4][4];
            uint32_t bfr[2][2][4];
            const uint32_t a_chk = (uint32_t)(kk * 2) + a_chk_l;
            const uint32_t b_chk = (uint32_t)(kk * 2) + b_chk_l;
#pragma unroll
            for (int mt = 0; mt < 4; mt++) {
                const uint32_t ro = swz((uint32_t)(wm * 64 + mt * 16) + a_row_l, a_chk);
                ldsm_x4(af[0][mt], base + 0 * TILE_B + ro);
                ldsm_x4(af[1][mt], base + 1 * TILE_B + ro);
            }
#pragma unroll
            for (int p = 0; p < 2; p++) {
                const uint32_t ro = swz((uint32_t)(wn * 32 + p * 16) + b_row_l, b_chk);
                ldsm_x4(bfr[0][p], base + 2 * TILE_B + ro);
                ldsm_x4(bfr[1][p], base + 3 * TILE_B + ro);
            }
#pragma unroll
            for (int ps = 0; ps < 3; ps++) {
                const int ah = (ps == 2), bh = (ps == 1);
#pragma unroll
                for (int mt = 0; mt < 4; mt++)
#pragma unroll
                    for (int nt = 0; nt < 4; nt++)
                        mma16816(acc[mt][nt], af[ah][mt],
                                 &bfr[bh][nt >> 1][(nt & 1) * 2]);
            }
        }
        st = (st == 2) ? 0 : st + 1;
        ls = (ls == 2) ? 0 : ls + 1;
    }

    // ---- epilogue ----
    const int tq = lane >> 2, tr = lane & 3;
#pragma unroll
    for (int nt = 0; nt < 4; nt++) {
        const int n = n0 + wn * 32 + nt * 8 + tr * 2;
        float b0 = 0.f, b1 = 0.f;
        if (HAS_BIAS) { b0 = bias[n]; b1 = bias[n + 1]; }
#pragma unroll
        for (int mt = 0; mt < 4; mt++) {
            const int m = m0 + wm * 64 + mt * 16 + tq;
            float2 o0, o1;
            o0.x = fmaf(alpha, acc[mt][nt][0], b0);
            o0.y = fmaf(alpha, acc[mt][nt][1], b1);
            o1.x = fmaf(alpha, acc[mt][nt][2], b0);
            o1.y = fmaf(alpha, acc[mt][nt][3], b1);
            const long long r0 = cz + (long long)m * ldc + n;
            const long long r1 = cz + (long long)(m + 8) * ldc + n;
            if (WRITE_F32) {
                *(float2*)(C + r0) = o0;
                *(float2*)(C + r1) = o1;
            }
            if (WRITE_SPLIT) {
                bf16 h0, l0, h1, l1;
                split1(o0.x, h0, l0); split1(o0.y, h1, l1);
                *(uint32_t*)(Oh + r0) = pack2(h0, h1);
                *(uint32_t*)(Ol + r0) = pack2(l0, l1);
                split1(o1.x, h0, l0); split1(o1.y, h1, l1);
                *(uint32_t*)(Oh + r1) = pack2(h0, h1);
                *(uint32_t*)(Ol + r1) = pack2(l0, l1);
            }
        }
    }
#undef LOAD_STAGE
}

// ---------------------------------------------------------------------------
__global__ __launch_bounds__(256)
void split_kernel(const float* __restrict__ in, bf16* __restrict__ oh,
                  bf16* __restrict__ ol)
{
    const size_t i = ((size_t)blockIdx.x * 256 + threadIdx.x) * 4;
    const float4 v = *(const float4*)(in + i);
    bf16 h0, h1, h2, h3, l0, l1, l2, l3;
    split1(v.x, h0, l0); split1(v.y, h1, l1);
    split1(v.z, h2, l2); split1(v.w, h3, l3);
    *(uint2*)(oh + i) = make_uint2(pack2(h0, h1), pack2(h2, h3));
    *(uint2*)(ol + i) = make_uint2(pack2(l0, l1), pack2(l2, l3));
}

// ---------------------------------------------------------------------------
__global__ __launch_bounds__(256)
void transpose_split(const float* __restrict__ in, int ldin, long long sIn,
                     bf16* __restrict__ oh, bf16* __restrict__ ol,
                     int R, long long sOut)
{
    __shared__ float t[32][33];
    in += blockIdx.z * sIn;
    oh += blockIdx.z * sOut;
    ol += blockIdx.z * sOut;
    const int c0 = blockIdx.x * 32, r0 = blockIdx.y * 32;
    const int x = threadIdx.x, y = threadIdx.y;
#pragma unroll
    for (int j = 0; j < 32; j += 8)
        t[y + j][x] = in[(long long)(r0 + y + j) * ldin + c0 + x];
    __syncthreads();
#pragma unroll
    for (int j = 0; j < 32; j += 8) {
        const float v = t[x][y + j];
        bf16 h, l;
        split1(v, h, l);
        oh[(long long)(c0 + y + j) * R + r0 + x] = h;
        ol[(long long)(c0 + y + j) * R + r0 + x] = l;
    }
}

// ---------------------------------------------------------------------------
__global__ __launch_bounds__(256)
void transpose_bf16_2(const bf16* __restrict__ inh, const bf16* __restrict__ inl,
                      int ldin, long long sIn,
                      bf16* __restrict__ oh, bf16* __restrict__ ol,
                      int R, long long sOut)
{
    __shared__ bf16 th[32][33];
    __shared__ bf16 tl[32][33];
    inh += blockIdx.z * sIn;
    inl += blockIdx.z * sIn;
    oh  += blockIdx.z * sOut;
    ol  += blockIdx.z * sOut;
    const int c0 = blockIdx.x * 32, r0 = blockIdx.y * 32;
    const int x = threadIdx.x, y = threadIdx.y;
#pragma unroll
    for (int j = 0; j < 32; j += 8) {
        th[y + j][x] = inh[(long long)(r0 + y + j) * ldin + c0 + x];
        tl[y + j][x] = inl[(long long)(r0 + y + j) * ldin + c0 + x];
    }
    __syncthreads();
#pragma unroll
    for (int j = 0; j < 32; j += 8) {
        oh[(long long)(c0 + y + j) * R + r0 + x] = th[x][y + j];
        ol[(long long)(c0 + y + j) * R + r0 + x] = tl[x][y + j];
    }
}

// ---------------------------------------------------------------------------
__global__ __launch_bounds__(256)
void wvec_kernel(const float* __restrict__ w_qkv, const float* __restrict__ bq,
                 float* __restrict__ wv)
{
    __shared__ float red[8];
    const int d = blockIdx.x;
    const float* rowp = w_qkv + (size_t)d * QKVC + D_;
    float s = 0.0f;
    for (int a = threadIdx.x; a < D_; a += 256) s += rowp[a] * bq[a];
#pragma unroll
    for (int o = 16; o > 0; o >>= 1) s += __shfl_xor_sync(0xffffffffu, s, o);
    if (!(threadIdx.x & 31)) red[threadIdx.x >> 5] = s;
    __syncthreads();
    if (threadIdx.x == 0) {
        float t = 0.0f;
#pragma unroll
        for (int i = 0; i < 8; i++) t += red[i];
        wv[d] = t;
    }
}

// ---------------------------------------------------------------------------
__global__ __launch_bounds__(256)
void cvec_kernel(const float* __restrict__ x, const float* __restrict__ wv,
                 float* __restrict__ c)
{
    const int row = blockIdx.x * 8 + (threadIdx.x >> 5);
    const int lane = threadIdx.x & 31;
    const float* xr = x + (size_t)row * D_;
    float s = 0.0f;
    for (int d = lane; d < D_; d += 32) s += xr[d] * wv[d];
#pragma unroll
    for (int o = 16; o > 0; o >>= 1) s += __shfl_xor_sync(0xffffffffu, s, o);
    if (lane == 0) c[row] = s * SCALE_F;
}

// ---------------------------------------------------------------------------
// concatenated bias: [0 x D_, b_qkv[2D..3D)]
__global__ __launch_bounds__(256)
void biascat_kernel(const float* __restrict__ bq, float* __restrict__ bc)
{
    const int i = blockIdx.x * 256 + threadIdx.x;
    if (i < NCAT) bc[i] = (i < D_) ? 0.0f : bq[2 * D_ + (i - D_)];
}

// ---------------------------------------------------------------------------
__global__ __launch_bounds__(256)
void softmax_split_kernel(const float* __restrict__ S, bf16* __restrict__ Sh,
                          bf16* __restrict__ Sl)
{
    const size_t ro = (size_t)blockIdx.x * N_;
    const float* p = S + ro;
    const int tid = threadIdx.x;
    const int w = tid >> 5, l = tid & 31;

    float4 v[4];
#pragma unroll
    for (int i = 0; i < 4; i++)
        v[i] = *(const float4*)(p + (size_t)(tid + i * 256) * 4);

    float m = v[0].x;
#pragma unroll
    for (int i = 0; i < 4; i++) {
        m = fmaxf(m, v[i].x); m = fmaxf(m, v[i].y);
        m = fmaxf(m, v[i].z); m = fmaxf(m, v[i].w);
    }
#pragma unroll
    for (int o = 16; o > 0; o >>= 1)
        m = fmaxf(m, __shfl_xor_sync(0xffffffffu, m, o));

    __shared__ float red[8];
    if (l == 0) red[w] = m;
    __syncthreads();
    float bm = red[0];
#pragma unroll
    for (int i = 1; i < 8; i++) bm = fmaxf(bm, red[i]);
    __syncthreads();

    float s = 0.0f;
#pragma unroll
    for (int i = 0; i < 4; i++) {
        v[i].x = expf(v[i].x - bm); s += v[i].x;
        v[i].y = expf(v[i].y - bm); s += v[i].y;
        v[i].z = expf(v[i].z - bm); s += v[i].z;
        v[i].w = expf(v[i].w - bm); s += v[i].w;
    }
#pragma unroll
    for (int o = 16; o > 0; o >>= 1)
        s += __shfl_xor_sync(0xffffffffu, s, o);
    if (l == 0) red[w] = s;
    __syncthreads();
    float tot = red[0];
#pragma unroll
    for (int i = 1; i < 8; i++) tot += red[i];
    const float inv = 1.0f / tot;

#pragma unroll
    for (int i = 0; i < 4; i++) {
        const size_t o = ro + (size_t)(tid + i * 256) * 4;
        bf16 h0, h1, h2, h3, l0, l1, l2, l3;
        split1(v[i].x * inv, h0, l0);
        split1(v[i].y * inv, h1, l1);
        split1(v[i].z * inv, h2, l2);
        split1(v[i].w * inv, h3, l3);
        *(uint2*)(Sh + o) = make_uint2(pack2(h0, h1), pack2(h2, h3));
        *(uint2*)(Sl + o) = make_uint2(pack2(l0, l1), pack2(l2, l3));
    }
}

// ---------------------------------------------------------------------------
extern "C" void kernel_launch(void* const* d_in, const int* in_sizes, int n_in,
                              void* d_out, int out_size)
{
    const float* x     = (const float*)d_in[0];
    const float* w_qkv = (const float*)d_in[1];
    const float* b_qkv = (const float*)d_in[2];
    const float* w_out = (const float*)d_in[3];
    const float* b_out = (const float*)d_in[4];
    float* out = (float*)d_out;

    float *S, *wv, *cvec, *bcat;
    bf16 *xh, *xl, *wrh, *wrl, *bch, *bcl, *yvh, *yvl;
    bf16 *sh, *sl, *vth, *vtl, *ch, *cl, *woh, *wol;
    cudaGetSymbolAddress((void**)&S,    g_s);
    cudaGetSymbolAddress((void**)&wv,   g_wv);
    cudaGetSymbolAddress((void**)&cvec, g_cvec);
    cudaGetSymbolAddress((void**)&bcat, g_bcat);
    cudaGetSymbolAddress((void**)&xh,   g_xh);  cudaGetSymbolAddress((void**)&xl,  g_xl);
    cudaGetSymbolAddress((void**)&wrh,  g_wrh); cudaGetSymbolAddress((void**)&wrl, g_wrl);
    cudaGetSymbolAddress((void**)&bch,  g_bch); cudaGetSymbolAddress((void**)&bcl, g_bcl);
    cudaGetSymbolAddress((void**)&yvh,  g_yvh); cudaGetSymbolAddress((void**)&yvl, g_yvl);
    cudaGetSymbolAddress((void**)&sh,   g_sh);  cudaGetSymbolAddress((void**)&sl,  g_sl);
    cudaGetSymbolAddress((void**)&vth,  g_vth); cudaGetSymbolAddress((void**)&vtl, g_vtl);
    cudaGetSymbolAddress((void**)&ch,   g_ch);  cudaGetSymbolAddress((void**)&cl,  g_cl);
    cudaGetSymbolAddress((void**)&woh,  g_woh); cudaGetSymbolAddress((void**)&wol, g_wol);

    cudaFuncSetAttribute(mma_gemm<true, false, true>,
        cudaFuncAttributeMaxDynamicSharedMemorySize, SMEM_DYN);
    cudaFuncSetAttribute(mma_gemm<false, false, true>,
        cudaFuncAttributeMaxDynamicSharedMemorySize, SMEM_DYN);
    cudaFuncSetAttribute(mma_gemm<true, true, false>,
        cudaFuncAttributeMaxDynamicSharedMemorySize, SMEM_DYN);

    // ONE side stream (known-guard-legal footprint) + events
    static cudaStream_t sv = nullptr;
    static cudaEvent_t eRoot = nullptr, eW = nullptr, eMain = nullptr,
                       eSv = nullptr;
    if (!sv) {
        cudaStreamCreateWithFlags(&sv, cudaStreamNonBlocking);
        cudaEventCreateWithFlags(&eRoot, cudaEventDisableTiming);
        cudaEventCreateWithFlags(&eW,    cudaEventDisableTiming);
        cudaEventCreateWithFlags(&eMain, cudaEventDisableTiming);
        cudaEventCreateWithFlags(&eSv,   cudaEventDisableTiming);
    }

    const dim3 blk(256);
    const dim3 tblk(32, 8);
    const long long ND  = (long long)N_ * D_;
    const long long NN  = (long long)N_ * N_;
    const long long DN  = (long long)D_ * N_;
    const long long NYV = (long long)N_ * NCAT;

    // ---- fork sv ----
    cudaEventRecord(eRoot, 0);
    cudaStreamWaitEvent(sv, eRoot, 0);

    // sv: weight transposes into bc rows [768,1536) and Wo^T (inputs only)
    transpose_split<<<dim3(D_ / 32, D_ / 32, 1), tblk, 0, sv>>>(
        w_qkv + 2 * D_, QKVC, 0, bch + (size_t)D_ * D_, bcl + (size_t)D_ * D_,
        D_, 0);                                                   // Wv^T
    transpose_split<<<dim3(D_ / 32, D_ / 32, 1), tblk, 0, sv>>>(
        w_out, D_, 0, woh, wol, D_, 0);                           // Wo^T
    cudaEventRecord(eW, sv);

    // main: x split, weight row split, bias vectors, Mt -> bc rows [0,768)
    split_kernel<<<(B_ * N_ * D_) / 1024, blk>>>(x, xh, xl);
    split_kernel<<<(D_ * QKVC) / 1024, blk>>>(w_qkv, wrh, wrl);
    wvec_kernel<<<D_, blk>>>(w_qkv, b_qkv, wv);
    cvec_kernel<<<(B_ * N_) / 8, blk>>>(x, wv, cvec);
    biascat_kernel<<<NCAT / 256, blk>>>(b_qkv, bcat);
    mma_gemm<false, false, true><<<dim3(D_ / 128, D_ / 128, 1), blk, SMEM_DYN>>>(
        wrh + D_, wrl + D_, wrh, wrl, nullptr, nullptr, bch, bcl,
        D_, QKVC, QKVC, D_, 0, 0, 0, 0, 1.0f);
    cudaEventRecord(eMain, 0);   // covers xh/xl, cvec, bcat, Mt

    // chains need: eMain (stream 0 has it implicitly) + eW (Wv^T in bc)
    cudaStreamWaitEvent(0,  eW,    0);
    cudaStreamWaitEvent(sv, eMain, 0);

    // ---- per-batch chains: batches 0,2 on stream 0; batches 1,3 on sv ----
    for (int b = 0; b < B_; b++) {
        cudaStream_t cs = (b & 1) ? sv : (cudaStream_t)0;
        const long long oND = (long long)b * ND;
        const long long oNN = (long long)b * NN;
        const long long oDN = (long long)b * DN;
        const long long oYV = (long long)b * NYV;

        // yv_b = x_b @ bc^T + [0,b_v]   (cols 0..767 = y_b, 768..1535 = V_b)
        mma_gemm<true, false, true><<<dim3(NCAT / 128, N_ / 128, 1), blk, SMEM_DYN, cs>>>(
            xh + oND, xl + oND, bch, bcl, bcat, nullptr, yvh + oYV, yvl + oYV,
            D_, D_, D_, NCAT, 0, 0, 0, 0, 1.0f);

        // V_b^T from yv cols [768,1536)
        transpose_bf16_2<<<dim3(D_ / 32, N_ / 32, 1), tblk, 0, cs>>>(
            yvh + oYV + D_, yvl + oYV + D_, NCAT, 0, vth + oDN, vtl + oDN,
            N_, 0);

        // S_b = scale*(y_b x_b^T) + cvec_b   (A rows stride NCAT)
        mma_gemm<true, true, false><<<dim3(N_ / 128, N_ / 128, 1), blk, SMEM_DYN, cs>>>(
            yvh + oYV, yvl + oYV, xh + oND, xl + oND, cvec + (long long)b * N_,
            S + oNN, nullptr, nullptr,
            D_, NCAT, D_, N_, 0, 0, 0, 0, SCALE_F);

        // softmax_b + split
        softmax_split_kernel<<<N_, blk, 0, cs>>>(S + oNN, sh + oNN, sl + oNN);

        // PV_b
        mma_gemm<false, false, true><<<dim3(D_ / 128, N_ / 128, 1), blk, SMEM_DYN, cs>>>(
            sh + oNN, sl + oNN, vth + oDN, vtl + oDN, nullptr, nullptr,
            ch + oND, cl + oND, N_, N_, N_, D_, 0, 0, 0, 0, 1.0f);

        // out_b = ctx_b @ Wo + bo
        mma_gemm<true, true, false><<<dim3(D_ / 128, N_ / 128, 1), blk, SMEM_DYN, cs>>>(
            ch + oND, cl + oND, woh, wol, b_out, out + oND, nullptr, nullptr,
            D_, D_, D_, D_, 0, 0, 0, 0, 1.0f);
    }

    // ---- join sv back to the capture stream ----
    cudaEventRecord(eSv, sv);
    cudaStreamWaitEvent(0, eSv, 0);
}

// round 17
// speedup vs baseline: 1.0420x; 1.0152x over previous
#include <cuda_runtime.h>
#include <cuda_bf16.h>
#include <stdint.h>
#include <math.h>

// ---------------------------------------------------------------------------
// MySelfAttention_V2 (B=4, N=4096, D=768) — mma.sync bf16 hi/lo split (3-pass)
// R15: R12 graph with one fix — the eV (V^T ready) wait on stream 0 moves
//      from before the chain loop to immediately before PV_0, so y0/S0/
//      softmax0 no longer stall ~150us behind the V path. Numerics identical.
// ---------------------------------------------------------------------------

#define B_   4
#define N_   4096
#define D_   768
#define QKVC 2304
#define SCALE_F 0.03608439182435161f

typedef __nv_bfloat16 bf16;

// ---------------- scratch (static device globals: allocation-guard-safe) ----
__device__ float g_s    [(size_t)B_ * N_ * N_];
__device__ bf16  g_xh   [(size_t)B_ * N_ * D_],  g_xl  [(size_t)B_ * N_ * D_];
__device__ bf16  g_wrh  [(size_t)D_ * QKVC],     g_wrl [(size_t)D_ * QKVC];
__device__ bf16  g_mth  [(size_t)D_ * D_],       g_mtl [(size_t)D_ * D_];
__device__ bf16  g_wvh  [(size_t)D_ * D_],       g_wvl [(size_t)D_ * D_];
__device__ bf16  g_vh   [(size_t)B_ * N_ * D_],  g_vl  [(size_t)B_ * N_ * D_];
__device__ bf16  g_yh   [(size_t)B_ * N_ * D_],  g_yl  [(size_t)B_ * N_ * D_];
__device__ bf16  g_sh   [(size_t)B_ * N_ * N_],  g_sl  [(size_t)B_ * N_ * N_];
__device__ bf16  g_vth  [(size_t)B_ * D_ * N_],  g_vtl [(size_t)B_ * D_ * N_];
__device__ bf16  g_ch   [(size_t)B_ * N_ * D_],  g_cl  [(size_t)B_ * N_ * D_];
__device__ bf16  g_woh  [(size_t)D_ * D_],       g_wol [(size_t)D_ * D_];
__device__ float g_wv   [D_];
__device__ float g_cvec [(size_t)B_ * N_];

// ---------------- PTX helpers ----------------------------------------------
static __device__ __forceinline__ uint32_t smem_u32(const void* p) {
    uint32_t a;
    asm("{ .reg .u64 t; cvta.to.shared.u64 t, %1; cvt.u32.u64 %0, t; }"
        : "=r"(a) : "l"(p));
    return a;
}
static __device__ __forceinline__ void cp_async16(uint32_t saddr, const void* g) {
    asm volatile("cp.async.cg.shared.global [%0], [%1], 16;"
                 :: "r"(saddr), "l"(g) : "memory");
}
static __device__ __forceinline__ void cp_commit() {
    asm volatile("cp.async.commit_group;" ::: "memory");
}
template <int N>
static __device__ __forceinline__ void cp_wait() {
    asm volatile("cp.async.wait_group %0;" :: "n"(N) : "memory");
}
static __device__ __forceinline__ void ldsm_x4(uint32_t* r, uint32_t addr) {
    asm volatile("ldmatrix.sync.aligned.m8n8.x4.shared.b16 {%0,%1,%2,%3}, [%4];"
                 : "=r"(r[0]), "=r"(r[1]), "=r"(r[2]), "=r"(r[3]) : "r"(addr));
}
static __device__ __forceinline__ void mma16816(float* c, const uint32_t* a,
                                                const uint32_t* b) {
    asm volatile(
        "mma.sync.aligned.m16n8k16.row.col.f32.bf16.bf16.f32 "
        "{%0,%1,%2,%3}, {%4,%5,%6,%7}, {%8,%9}, {%0,%1,%2,%3};"
        : "+f"(c[0]), "+f"(c[1]), "+f"(c[2]), "+f"(c[3])
        : "r"(a[0]), "r"(a[1]), "r"(a[2]), "r"(a[3]), "r"(b[0]), "r"(b[1]));
}
static __device__ __forceinline__ void split1(float v, bf16& h, bf16& l) {
    h = __float2bfloat16_rn(v);
    l = __float2bfloat16_rn(v - __bfloat162float(h));
}
static __device__ __forceinline__ uint32_t pack2(bf16 a, bf16 b) {
    return (uint32_t)__bfloat16_as_ushort(a) |
           ((uint32_t)__bfloat16_as_ushort(b) << 16);
}
static __device__ __forceinline__ uint32_t swz(uint32_t row, uint32_t chunk) {
    return row * 64u + (((chunk ^ (row >> 1)) & 3u) << 4);
}

// ---------------------------------------------------------------------------
// GEMM (R12 core): C[m,n] = alpha * sum_k A[m,k]*B[n,k] (+bias[n])
// ---------------------------------------------------------------------------
#define TILE_B 8192                       // 128 rows * 64 B
#define STAGE_B (4 * TILE_B)              // Ah,Al,Bh,Bl
static const int SMEM_DYN = 3 * STAGE_B;  // 98304

template <bool HAS_BIAS, bool WRITE_F32, bool WRITE_SPLIT>
__global__ __launch_bounds__(256, 2)
void mma_gemm(const bf16* __restrict__ Ah, const bf16* __restrict__ Al,
              const bf16* __restrict__ Bh, const bf16* __restrict__ Bl,
              const float* __restrict__ bias, float* __restrict__ C,
              bf16* __restrict__ Oh, bf16* __restrict__ Ol,
              int K, int lda, int ldb, int ldc,
              long long sA, long long sB, long long sC, long long sBias,
              float alpha)
{
    extern __shared__ char smem[];
    const uint32_t sb = smem_u32(smem);

    Ah += blockIdx.z * sA;  Al += blockIdx.z * sA;
    Bh += blockIdx.z * sB;  Bl += blockIdx.z * sB;
    if (HAS_BIAS) bias += blockIdx.z * sBias;
    const long long cz = blockIdx.z * sC;
    const int m0 = blockIdx.y * 128, n0 = blockIdx.x * 128;
    const int tid  = threadIdx.x;
    const int wid  = tid >> 5, lane = tid & 31;
    const int wm   = wid >> 2, wn = wid & 3;   // 2 x 4 warps

    const int cr0 = tid >> 2, cc = tid & 3;
    const uint32_t so0 = swz((uint32_t)cr0, (uint32_t)cc);
    const uint32_t so1 = swz((uint32_t)(cr0 + 64), (uint32_t)cc);

#define LOAD_STAGE(st, k0)                                                      \
    do {                                                                        \
        const uint32_t s0 = sb + (uint32_t)(st) * STAGE_B;                      \
        const long long kof = (long long)(k0) + cc * 8;                         \
        cp_async16(s0 + 0*TILE_B + so0, Ah + (long long)(m0+cr0)    *lda + kof);\
        cp_async16(s0 + 0*TILE_B + so1, Ah + (long long)(m0+cr0+64) *lda + kof);\
        cp_async16(s0 + 1*TILE_B + so0, Al + (long long)(m0+cr0)    *lda + kof);\
        cp_async16(s0 + 1*TILE_B + so1, Al + (long long)(m0+cr0+64) *lda + kof);\
        cp_async16(s0 + 2*TILE_B + so0, Bh + (long long)(n0+cr0)    *ldb + kof);\
        cp_async16(s0 + 2*TILE_B + so1, Bh + (long long)(n0+cr0+64) *ldb + kof);\
        cp_async16(s0 + 3*TILE_B + so0, Bl + (long long)(n0+cr0)    *ldb + kof);\
        cp_async16(s0 + 3*TILE_B + so1, Bl + (long long)(n0+cr0+64) *ldb + kof);\
    } while (0)

    const uint32_t a_row_l = (uint32_t)(lane & 15);
    const uint32_t a_chk_l = (uint32_t)(lane >> 4);
    const uint32_t b_row_l = (uint32_t)((lane & 7) + ((lane >> 4) << 3));
    const uint32_t b_chk_l = (uint32_t)((lane >> 3) & 1);

    float acc[4][4][4];
#pragma unroll
    for (int mt = 0; mt < 4; mt++)
#pragma unroll
        for (int nt = 0; nt < 4; nt++)
#pragma unroll
            for (int r = 0; r < 4; r++) acc[mt][nt][r] = 0.0f;

    const int nch = K / 32;
    LOAD_STAGE(0, 0);
    cp_commit();
    if (nch > 1) LOAD_STAGE(1, 32);
    cp_commit();

    int st = 0, ls = 2;
    for (int ch = 0; ch < nch; ch++) {
        cp_wait<1>();
        __syncthreads();
        if (ch + 2 < nch) LOAD_STAGE(ls, (long long)(ch + 2) * 32);
        cp_commit();

        const uint32_t base = sb + (uint32_t)st * STAGE_B;
#pragma unroll
        for (int kk = 0; kk < 2; kk++) {
            uint32_t af[2][4][4];
            uint32_t bfr[2][2][4];
            const uint32_t a_chk = (uint32_t)(kk * 2) + a_chk_l;
            const uint32_t b_chk = (uint32_t)(kk * 2) + b_chk_l;
#pragma unroll
            for (int mt = 0; mt < 4; mt++) {
                const uint32_t ro = swz((uint32_t)(wm * 64 + mt * 16) + a_row_l, a_chk);
                ldsm_x4(af[0][mt], base + 0 * TILE_B + ro);
                ldsm_x4(af[1][mt], base + 1 * TILE_B + ro);
            }
#pragma unroll
            for (int p = 0; p < 2; p++) {
                const uint32_t ro = swz((uint32_t)(wn * 32 + p * 16) + b_row_l, b_chk);
                ldsm_x4(bfr[0][p], base + 2 * TILE_B + ro);
                ldsm_x4(bfr[1][p], base + 3 * TILE_B + ro);
            }
#pragma unroll
            for (int ps = 0; ps < 3; ps++) {
                const int ah = (ps == 2), bh = (ps == 1);
#pragma unroll
                for (int mt = 0; mt < 4; mt++)
#pragma unroll
                    for (int nt = 0; nt < 4; nt++)
                        mma16816(acc[mt][nt], af[ah][mt],
                                 &bfr[bh][nt >> 1][(nt & 1) * 2]);
            }
        }
        st = (st == 2) ? 0 : st + 1;
        ls = (ls == 2) ? 0 : ls + 1;
    }

    // ---- epilogue ----
    const int tq = lane >> 2, tr = lane & 3;
#pragma unroll
    for (int nt = 0; nt < 4; nt++) {
        const int n = n0 + wn * 32 + nt * 8 + tr * 2;
        float b0 = 0.f, b1 = 0.f;
        if (HAS_BIAS) { b0 = bias[n]; b1 = bias[n + 1]; }
#pragma unroll
        for (int mt = 0; mt < 4; mt++) {
            const int m = m0 + wm * 64 + mt * 16 + tq;
            float2 o0, o1;
            o0.x = fmaf(alpha, acc[mt][nt][0], b0);
            o0.y = fmaf(alpha, acc[mt][nt][1], b1);
            o1.x = fmaf(alpha, acc[mt][nt][2], b0);
            o1.y = fmaf(alpha, acc[mt][nt][3], b1);
            const long long r0 = cz + (long long)m * ldc + n;
            const long long r1 = cz + (long long)(m + 8) * ldc + n;
            if (WRITE_F32) {
                *(float2*)(C + r0) = o0;
                *(float2*)(C + r1) = o1;
            }
            if (WRITE_SPLIT) {
                bf16 h0, l0, h1, l1;
                split1(o0.x, h0, l0); split1(o0.y, h1, l1);
                *(uint32_t*)(Oh + r0) = pack2(h0, h1);
                *(uint32_t*)(Ol + r0) = pack2(l0, l1);
                split1(o1.x, h0, l0); split1(o1.y, h1, l1);
                *(uint32_t*)(Oh + r1) = pack2(h0, h1);
                *(uint32_t*)(Ol + r1) = pack2(l0, l1);
            }
        }
    }
#undef LOAD_STAGE
}

// ---------------------------------------------------------------------------
__global__ __launch_bounds__(256)
void split_kernel(const float* __restrict__ in, bf16* __restrict__ oh,
                  bf16* __restrict__ ol)
{
    const size_t i = ((size_t)blockIdx.x * 256 + threadIdx.x) * 4;
    const float4 v = *(const float4*)(in + i);
    bf16 h0, h1, h2, h3, l0, l1, l2, l3;
    split1(v.x, h0, l0); split1(v.y, h1, l1);
    split1(v.z, h2, l2); split1(v.w, h3, l3);
    *(uint2*)(oh + i) = make_uint2(pack2(h0, h1), pack2(h2, h3));
    *(uint2*)(ol + i) = make_uint2(pack2(l0, l1), pack2(l2, l3));
}

// ---------------------------------------------------------------------------
__global__ __launch_bounds__(256)
void transpose_split(const float* __restrict__ in, int ldin, long long sIn,
                     bf16* __restrict__ oh, bf16* __restrict__ ol,
                     int R, long long sOut)
{
    __shared__ float t[32][33];
    in += blockIdx.z * sIn;
    oh += blockIdx.z * sOut;
    ol += blockIdx.z * sOut;
    const int c0 = blockIdx.x * 32, r0 = blockIdx.y * 32;
    const int x = threadIdx.x, y = threadIdx.y;
#pragma unroll
    for (int j = 0; j < 32; j += 8)
        t[y + j][x] = in[(long long)(r0 + y + j) * ldin + c0 + x];
    __syncthreads();
#pragma unroll
    for (int j = 0; j < 32; j += 8) {
        const float v = t[x][y + j];
        bf16 h, l;
        split1(v, h, l);
        oh[(long long)(c0 + y + j) * R + r0 + x] = h;
        ol[(long long)(c0 + y + j) * R + r0 + x] = l;
    }
}

// ---------------------------------------------------------------------------
__global__ __launch_bounds__(256)
void transpose_bf16_2(const bf16* __restrict__ inh, const bf16* __restrict__ inl,
                      int ldin, long long sIn,
                      bf16* __restrict__ oh, bf16* __restrict__ ol,
                      int R, long long sOut)
{
    __shared__ bf16 th[32][33];
    __shared__ bf16 tl[32][33];
    inh += blockIdx.z * sIn;
    inl += blockIdx.z * sIn;
    oh  += blockIdx.z * sOut;
    ol  += blockIdx.z * sOut;
    const int c0 = blockIdx.x * 32, r0 = blockIdx.y * 32;
    const int x = threadIdx.x, y = threadIdx.y;
#pragma unroll
    for (int j = 0; j < 32; j += 8) {
        th[y + j][x] = inh[(long long)(r0 + y + j) * ldin + c0 + x];
        tl[y + j][x] = inl[(long long)(r0 + y + j) * ldin + c0 + x];
    }
    __syncthreads();
#pragma unroll
    for (int j = 0; j < 32; j += 8) {
        oh[(long long)(c0 + y + j) * R + r0 + x] = th[x][y + j];
        ol[(long long)(c0 + y + j) * R + r0 + x] = tl[x][y + j];
    }
}

// ---------------------------------------------------------------------------
__global__ __launch_bounds__(256)
void wvec_kernel(const float* __restrict__ w_qkv, const float* __restrict__ bq,
                 float* __restrict__ wv)
{
    __shared__ float red[8];
    const int d = blockIdx.x;
    const float* rowp = w_qkv + (size_t)d * QKVC + D_;
    float s = 0.0f;
    for (int a = threadIdx.x; a < D_; a += 256) s += rowp[a] * bq[a];
#pragma unroll
    for (int o = 16; o > 0; o >>= 1) s += __shfl_xor_sync(0xffffffffu, s, o);
    if (!(threadIdx.x & 31)) red[threadIdx.x >> 5] = s;
    __syncthreads();
    if (threadIdx.x == 0) {
        float t = 0.0f;
#pragma unroll
        for (int i = 0; i < 8; i++) t += red[i];
        wv[d] = t;
    }
}

// ---------------------------------------------------------------------------
__global__ __launch_bounds__(256)
void cvec_kernel(const float* __restrict__ x, const float* __restrict__ wv,
                 float* __restrict__ c)
{
    const int row = blockIdx.x * 8 + (threadIdx.x >> 5);
    const int lane = threadIdx.x & 31;
    const float* xr = x + (size_t)row * D_;
    float s = 0.0f;
    for (int d = lane; d < D_; d += 32) s += xr[d] * wv[d];
#pragma unroll
    for (int o = 16; o > 0; o >>= 1) s += __shfl_xor_sync(0xffffffffu, s, o);
    if (lane == 0) c[row] = s * SCALE_F;
}

// ---------------------------------------------------------------------------
__global__ __launch_bounds__(256)
void softmax_split_kernel(const float* __restrict__ S, bf16* __restrict__ Sh,
                          bf16* __restrict__ Sl)
{
    const size_t ro = (size_t)blockIdx.x * N_;
    const float* p = S + ro;
    const int tid = threadIdx.x;
    const int w = tid >> 5, l = tid & 31;

    float4 v[4];
#pragma unroll
    for (int i = 0; i < 4; i++)
        v[i] = *(const float4*)(p + (size_t)(tid + i * 256) * 4);

    float m = v[0].x;
#pragma unroll
    for (int i = 0; i < 4; i++) {
        m = fmaxf(m, v[i].x); m = fmaxf(m, v[i].y);
        m = fmaxf(m, v[i].z); m = fmaxf(m, v[i].w);
    }
#pragma unroll
    for (int o = 16; o > 0; o >>= 1)
        m = fmaxf(m, __shfl_xor_sync(0xffffffffu, m, o));

    __shared__ float red[8];
    if (l == 0) red[w] = m;
    __syncthreads();
    float bm = red[0];
#pragma unroll
    for (int i = 1; i < 8; i++) bm = fmaxf(bm, red[i]);
    __syncthreads();

    float s = 0.0f;
#pragma unroll
    for (int i = 0; i < 4; i++) {
        v[i].x = expf(v[i].x - bm); s += v[i].x;
        v[i].y = expf(v[i].y - bm); s += v[i].y;
        v[i].z = expf(v[i].z - bm); s += v[i].z;
        v[i].w = expf(v[i].w - bm); s += v[i].w;
    }
#pragma unroll
    for (int o = 16; o > 0; o >>= 1)
        s += __shfl_xor_sync(0xffffffffu, s, o);
    if (l == 0) red[w] = s;
    __syncthreads();
    float tot = red[0];
#pragma unroll
    for (int i = 1; i < 8; i++) tot += red[i];
    const float inv = 1.0f / tot;

#pragma unroll
    for (int i = 0; i < 4; i++) {
        const size_t o = ro + (size_t)(tid + i * 256) * 4;
        bf16 h0, h1, h2, h3, l0, l1, l2, l3;
        split1(v[i].x * inv, h0, l0);
        split1(v[i].y * inv, h1, l1);
        split1(v[i].z * inv, h2, l2);
        split1(v[i].w * inv, h3, l3);
        *(uint2*)(Sh + o) = make_uint2(pack2(h0, h1), pack2(h2, h3));
        *(uint2*)(Sl + o) = make_uint2(pack2(l0, l1), pack2(l2, l3));
    }
}

// ---------------------------------------------------------------------------
extern "C" void kernel_launch(void* const* d_in, const int* in_sizes, int n_in,
                              void* d_out, int out_size)
{
    const float* x     = (const float*)d_in[0];
    const float* w_qkv = (const float*)d_in[1];
    const float* b_qkv = (const float*)d_in[2];
    const float* w_out = (const float*)d_in[3];
    const float* b_out = (const float*)d_in[4];
    float* out = (float*)d_out;

    float *S, *wv, *cvec;
    bf16 *xh, *xl, *wrh, *wrl, *mth, *mtl, *wvh, *wvl, *vh, *vl, *yh, *yl;
    bf16 *sh, *sl, *vth, *vtl, *ch, *cl, *woh, *wol;
    cudaGetSymbolAddress((void**)&S,    g_s);
    cudaGetSymbolAddress((void**)&wv,   g_wv);
    cudaGetSymbolAddress((void**)&cvec, g_cvec);
    cudaGetSymbolAddress((void**)&xh,   g_xh);  cudaGetSymbolAddress((void**)&xl,  g_xl);
    cudaGetSymbolAddress((void**)&wrh,  g_wrh); cudaGetSymbolAddress((void**)&wrl, g_wrl);
    cudaGetSymbolAddress((void**)&mth,  g_mth); cudaGetSymbolAddress((void**)&mtl, g_mtl);
    cudaGetSymbolAddress((void**)&wvh,  g_wvh); cudaGetSymbolAddress((void**)&wvl, g_wvl);
    cudaGetSymbolAddress((void**)&vh,   g_vh);  cudaGetSymbolAddress((void**)&vl,  g_vl);
    cudaGetSymbolAddress((void**)&yh,   g_yh);  cudaGetSymbolAddress((void**)&yl,  g_yl);
    cudaGetSymbolAddress((void**)&sh,   g_sh);  cudaGetSymbolAddress((void**)&sl,  g_sl);
    cudaGetSymbolAddress((void**)&vth,  g_vth); cudaGetSymbolAddress((void**)&vtl, g_vtl);
    cudaGetSymbolAddress((void**)&ch,   g_ch);  cudaGetSymbolAddress((void**)&cl,  g_cl);
    cudaGetSymbolAddress((void**)&woh,  g_woh); cudaGetSymbolAddress((void**)&wol, g_wol);

    cudaFuncSetAttribute(mma_gemm<true, false, true>,
        cudaFuncAttributeMaxDynamicSharedMemorySize, SMEM_DYN);
    cudaFuncSetAttribute(mma_gemm<false, false, true>,
        cudaFuncAttributeMaxDynamicSharedMemorySize, SMEM_DYN);
    cudaFuncSetAttribute(mma_gemm<true, true, false>,
        cudaFuncAttributeMaxDynamicSharedMemorySize, SMEM_DYN);

    // ONE side stream (known-guard-legal footprint) + events
    static cudaStream_t sv = nullptr;
    static cudaEvent_t eRoot = nullptr, eX = nullptr, eMain = nullptr,
                       eV = nullptr, eSv = nullptr;
    if (!sv) {
        cudaStreamCreateWithFlags(&sv, cudaStreamNonBlocking);
        cudaEventCreateWithFlags(&eRoot, cudaEventDisableTiming);
        cudaEventCreateWithFlags(&eX,    cudaEventDisableTiming);
        cudaEventCreateWithFlags(&eMain, cudaEventDisableTiming);
        cudaEventCreateWithFlags(&eV,    cudaEventDisableTiming);
        cudaEventCreateWithFlags(&eSv,   cudaEventDisableTiming);
    }

    const dim3 blk(256);
    const dim3 tblk(32, 8);
    const long long ND = (long long)N_ * D_;
    const long long NN = (long long)N_ * N_;
    const long long DN = (long long)D_ * N_;

    // ---- fork sv ----
    cudaEventRecord(eRoot, 0);
    cudaStreamWaitEvent(sv, eRoot, 0);

    // sv: weight transposes (inputs only)
    transpose_split<<<dim3(D_ / 32, D_ / 32, 1), tblk, 0, sv>>>(
        w_qkv + 2 * D_, QKVC, 0, wvh, wvl, D_, 0);                // Wv^T
    transpose_split<<<dim3(D_ / 32, D_ / 32, 1), tblk, 0, sv>>>(
        w_out, D_, 0, woh, wol, D_, 0);                           // Wo^T

    // main: x split, weight row split, bias vectors, Mt
    split_kernel<<<(B_ * N_ * D_) / 1024, blk>>>(x, xh, xl);
    cudaEventRecord(eX, 0);
    split_kernel<<<(D_ * QKVC) / 1024, blk>>>(w_qkv, wrh, wrl);
    wvec_kernel<<<D_, blk>>>(w_qkv, b_qkv, wv);
    cvec_kernel<<<(B_ * N_) / 8, blk>>>(x, wv, cvec);
    mma_gemm<false, false, true><<<dim3(D_ / 128, D_ / 128, 1), blk, SMEM_DYN>>>(
        wrh + D_, wrl + D_, wrh, wrl, nullptr, nullptr, mth, mtl,
        D_, QKVC, QKVC, D_, 0, 0, 0, 0, 1.0f);
    cudaEventRecord(eMain, 0);   // covers xh/xl, cvec, Mt

    // sv: V GEMM + V^T (needs xh/xl)
    cudaStreamWaitEvent(sv, eX, 0);
    mma_gemm<true, false, true><<<dim3(D_ / 128, (B_ * N_) / 128, 1), blk, SMEM_DYN, sv>>>(
        xh, xl, wvh, wvl, b_qkv + 2 * D_, nullptr, vh, vl,
        D_, D_, D_, D_, 0, 0, 0, 0, 1.0f);
    transpose_bf16_2<<<dim3(D_ / 32, N_ / 32, B_), tblk, 0, sv>>>(
        vh, vl, D_, ND, vth, vtl, N_, DN);
    cudaEventRecord(eV, sv);

    // sv chains need Mt/cvec (sv already ordered after its own V path)
    cudaStreamWaitEvent(sv, eMain, 0);

    // ---- per-batch chains: batches 0,2 on stream 0; batches 1,3 on sv ----
    for (int b = 0; b < B_; b++) {
        cudaStream_t cs = (b & 1) ? sv : (cudaStream_t)0;
        const long long oND = (long long)b * ND;
        const long long oNN = (long long)b * NN;
        const long long oDN = (long long)b * DN;

        // y_b = x_b @ Mt^T
        mma_gemm<false, false, true><<<dim3(D_ / 128, N_ / 128, 1), blk, SMEM_DYN, cs>>>(
            xh + oND, xl + oND, mth, mtl, nullptr, nullptr, yh + oND, yl + oND,
            D_, D_, D_, D_, 0, 0, 0, 0, 1.0f);

        // S_b = scale*(y_b x_b^T) + cvec_b
        mma_gemm<true, true, false><<<dim3(N_ / 128, N_ / 128, 1), blk, SMEM_DYN, cs>>>(
            yh + oND, yl + oND, xh + oND, xl + oND, cvec + (long long)b * N_,
            S + oNN, nullptr, nullptr,
            D_, D_, D_, N_, 0, 0, 0, 0, SCALE_F);

        // softmax_b + split
        softmax_split_kernel<<<N_, blk, 0, cs>>>(S + oNN, sh + oNN, sl + oNN);

        // PV_b — stream 0 needs V^T from sv; wait placed HERE (after y/S/
        // softmax have been enqueued) so those launches never stall on eV.
        if (b == 0) cudaStreamWaitEvent(0, eV, 0);
        mma_gemm<false, false, true><<<dim3(D_ / 128, N_ / 128, 1), blk, SMEM_DYN, cs>>>(
            sh + oNN, sl + oNN, vth + oDN, vtl + oDN, nullptr, nullptr,
            ch + oND, cl + oND, N_, N_, N_, D_, 0, 0, 0, 0, 1.0f);

        // out_b = ctx_b @ Wo + bo
        mma_gemm<true, true, false><<<dim3(D_ / 128, N_ / 128, 1), blk, SMEM_DYN, cs>>>(
            ch + oND, cl + oND, woh, wol, b_out, out + oND, nullptr, nullptr,
            D_, D_, D_, D_, 0, 0, 0, 0, 1.0f);
    }

    // ---- join sv back to the capture stream ----
    cudaEventRecord(eSv, sv);
    cudaStreamWaitEvent(0, eSv, 0);
}